// round 2
// baseline (speedup 1.0000x reference)
#include <cuda_runtime.h>
#include <cuda_bf16.h>

// Problem constants (fixed by the reference):
//   B=128, W=256, H=256, MAX_OBJS=128
// Inputs (metadata order):
//   d_in[0] loc_pred  f32 [128,256,256,4]
//   d_in[1] loc_true  f32 [128,128,4]
//   d_in[2] reg_mask  f32 [128,128]
//   d_in[3] indices   i32 [128,128,3]
// Output: f32 scalar.

#define NB    128    // blocks  (= B)
#define NT    128    // threads (= MAX_OBJS)
#define WH    65536  // W*H

__device__ float        g_loss_sum = 0.0f;
__device__ float        g_mask_sum = 0.0f;
__device__ unsigned int g_done     = 0;

__global__ void __launch_bounds__(NT) giou_loss_kernel(
    const float* __restrict__ loc_pred,
    const float* __restrict__ loc_true,
    const float* __restrict__ reg_mask,
    const int*   __restrict__ indices,
    float*       __restrict__ out)
{
    const int i = blockIdx.x * NT + threadIdx.x;   // box index in [0, 16384)

    // ---- issue all independent loads first (overlap their latency) ----
    const int bidx = __ldg(indices + (size_t)i * 3 + 0);
    const int pos  = __ldg(indices + (size_t)i * 3 + 1);
    const float4 t = *reinterpret_cast<const float4*>(loc_true + (size_t)i * 4);
    const float  m = __ldg(reg_mask + i);

    // ---- dependent gather: predicted box (16B aligned), normalize by 256 ----
    const float4 p = *reinterpret_cast<const float4*>(
        loc_pred + (((size_t)bidx << 16) + (size_t)pos) * 4);
    const float inv = 1.0f / 256.0f;
    const float b1y0 = p.x * inv, b1x0 = p.y * inv;
    const float b1y1 = p.z * inv, b1x1 = p.w * inv;

    const float b2y0 = t.x, b2x0 = t.y, b2y1 = t.z, b2x1 = t.w;

    // ---- GIoU (matching reference div_no_nan semantics) ----
    const float a1 = fmaxf(b1y1 - b1y0, 0.0f) * fmaxf(b1x1 - b1x0, 0.0f);
    const float a2 = fmaxf(b2y1 - b2y0, 0.0f) * fmaxf(b2x1 - b2x0, 0.0f);

    const float iy = fmaxf(fminf(b1y1, b2y1) - fmaxf(b1y0, b2y0), 0.0f);
    const float ix = fmaxf(fminf(b1x1, b2x1) - fmaxf(b1x0, b2x0), 0.0f);
    const float inter = iy * ix;
    const float uni   = a1 + a2 - inter;
    const float iou   = (uni != 0.0f) ? (inter / uni) : 0.0f;

    const float ey = fmaxf(fmaxf(b1y1, b2y1) - fminf(b1y0, b2y0), 0.0f);
    const float ex = fmaxf(fmaxf(b1x1, b2x1) - fminf(b1x0, b2x0), 0.0f);
    const float enc  = ey * ex;
    const float giou = iou - ((enc != 0.0f) ? ((enc - uni) / enc) : 0.0f);

    float loss = (1.0f - giou) * m;
    float mask = m;

    // ---- block reduction: 4 warps ----
    #pragma unroll
    for (int off = 16; off > 0; off >>= 1) {
        loss += __shfl_down_sync(0xFFFFFFFFu, loss, off);
        mask += __shfl_down_sync(0xFFFFFFFFu, mask, off);
    }
    __shared__ float s_loss[4], s_mask[4];
    const int lane = threadIdx.x & 31;
    const int warp = threadIdx.x >> 5;
    if (lane == 0) { s_loss[warp] = loss; s_mask[warp] = mask; }
    __syncthreads();

    if (threadIdx.x == 0) {
        float bl = s_loss[0] + s_loss[1] + s_loss[2] + s_loss[3];
        float bm = s_mask[0] + s_mask[1] + s_mask[2] + s_mask[3];
        atomicAdd(&g_loss_sum, bl);
        atomicAdd(&g_mask_sum, bm);
        __threadfence();
        const unsigned ticket = atomicAdd(&g_done, 1u);
        if (ticket == (unsigned)(gridDim.x - 1)) {
            // last block: finalize, then reset accumulators for the next
            // graph replay (statics are zero-init, so first call is correct).
            const float L = atomicExch(&g_loss_sum, 0.0f);
            const float M = atomicExch(&g_mask_sum, 0.0f);
            atomicExch(&g_done, 0u);
            out[0] = L / M;   // reference uses a plain divide here
        }
    }
}

extern "C" void kernel_launch(void* const* d_in, const int* in_sizes, int n_in,
                              void* d_out, int out_size)
{
    const float* loc_pred = (const float*)d_in[0];
    const float* loc_true = (const float*)d_in[1];
    const float* reg_mask = (const float*)d_in[2];
    const int*   indices  = (const int*)  d_in[3];
    float*       out      = (float*)d_out;
    (void)in_sizes; (void)n_in; (void)out_size;

    giou_loss_kernel<<<NB, NT>>>(loc_pred, loc_true, reg_mask, indices, out);
}